// round 14
// baseline (speedup 1.0000x reference)
#include <cuda_runtime.h>
#include <cuda_fp16.h>
#include <cstdint>

// ============================================================================
// Problem dims (fixed): x [4,2048,1024], E=8 experts, H=4096
// ============================================================================
static constexpr int NTOK = 8192;   // B*T
static constexpr int C    = 1024;
static constexpr int H    = 4096;
static constexpr int E    = 8;

static constexpr int BM = 128, BN = 64, BK = 128;
static constexpr int MAX_TILES = 72;    // sum ceil(cnt_e/BM) <= 64 + 7

// ============================================================================
// Scratch (static __device__ — no allocation allowed)
// ============================================================================
__device__ __half g_w1c[(size_t)E * C * H];   // fp16 copy of w1, [E][C][H] (K-major)
__device__ __half g_w2c[(size_t)E * H * C];   // fp16 copy of w2, [E][H][C] (K-major)
__device__ __half g_Xg [(size_t)NTOK * C];    // gathered tokens, fp16
__device__ __half g_Hg [(size_t)NTOK * H];    // hidden activations, fp16
__device__ int    g_top1[NTOK];
__device__ int    g_tokof[NTOK];
__device__ int    g_counts[E];
__device__ int    g_offsets[E];
__device__ int    g_cursors[E];
__device__ int    g_done;
__device__ int    g_ntiles;
__device__ int    g_tiles[MAX_TILES];          // (e << 16) | m_tile

#define DI __device__ __forceinline__

DI uint32_t smem_u32(const void* p) {
    uint32_t r;
    asm("{ .reg .u64 t; cvta.to.shared.u64 t, %1; cvt.u32.u64 %0, t; }"
        : "=r"(r) : "l"(p));
    return r;
}

// 16B async copy, zero-fill when srcsize==0
DI void cp16(uint32_t dst, const void* src, int srcsize) {
    asm volatile("cp.async.cg.shared.global [%0], [%1], 16, %2;"
                 :: "r"(dst), "l"(src), "r"(srcsize) : "memory");
}
#define CP_COMMIT() asm volatile("cp.async.commit_group;" ::: "memory")
#define CP_WAIT(n)  asm volatile("cp.async.wait_group %0;" :: "n"(n) : "memory")

DI void ldsm4(uint32_t* r, uint32_t addr) {
    asm volatile("ldmatrix.sync.aligned.m8n8.x4.shared.b16 {%0,%1,%2,%3}, [%4];"
                 : "=r"(r[0]), "=r"(r[1]), "=r"(r[2]), "=r"(r[3]) : "r"(addr));
}

DI void ldsm4t(uint32_t* r, uint32_t addr) {
    asm volatile("ldmatrix.sync.aligned.m8n8.x4.trans.shared.b16 {%0,%1,%2,%3}, [%4];"
                 : "=r"(r[0]), "=r"(r[1]), "=r"(r[2]), "=r"(r[3]) : "r"(addr));
}

DI void mma16816(float* d, const uint32_t* a, uint32_t b0, uint32_t b1) {
    asm volatile(
        "mma.sync.aligned.m16n8k16.row.col.f32.f16.f16.f32 "
        "{%0,%1,%2,%3}, {%4,%5,%6,%7}, {%8,%9}, {%0,%1,%2,%3};"
        : "+f"(d[0]), "+f"(d[1]), "+f"(d[2]), "+f"(d[3])
        : "r"(a[0]), "r"(a[1]), "r"(a[2]), "r"(a[3]), "r"(b0), "r"(b1));
}

// 128B tile rows (64 halves), 8x16B chunks, chunk ^= row&7.
DI uint32_t swz128(int row, int chunk) {
    return (uint32_t)(row * 128 + ((chunk ^ (row & 7)) << 4));
}
// 256B tile rows (128 halves), 16x16B chunks, chunk low-3-bits ^= row&7.
DI uint32_t swz256(int row, int chunk) {
    return (uint32_t)(row * 256 + ((chunk ^ (row & 7)) << 4));
}

// ============================================================================
// Stage 1: setup kernels
// ============================================================================

// Streaming fp32 -> fp16 convert of BOTH weight tensors (layout preserved).
__global__ void k_convert(const float* __restrict__ w1, const float* __restrict__ w2,
                          __half* __restrict__ w1c, __half* __restrict__ w2c,
                          int n4) {
    if (blockIdx.x == 0 && threadIdx.x <= E) {
        if (threadIdx.x < E) g_counts[threadIdx.x] = 0;
        else                 g_done = 0;
    }
    const int stride = gridDim.x * blockDim.x;
    for (int i = blockIdx.x * blockDim.x + threadIdx.x; i < 2 * n4; i += stride) {
        const bool second = (i >= n4);
        const int idx = second ? i - n4 : i;
        const float4 v = reinterpret_cast<const float4*>(second ? w2 : w1)[idx];
        __half2 h0 = __floats2half2_rn(v.x, v.y);
        __half2 h1 = __floats2half2_rn(v.z, v.w);
        uint2 pk;
        pk.x = *reinterpret_cast<uint32_t*>(&h0);
        pk.y = *reinterpret_cast<uint32_t*>(&h1);
        reinterpret_cast<uint2*>(second ? w2c : w1c)[idx] = pk;
    }
}

// Router + histogram + (last block) scan + tile table.
__global__ void k_router(const float* __restrict__ x,
                         const float* __restrict__ wr,
                         const float* __restrict__ br) {
    __shared__ int loc[E];
    if (threadIdx.x < E) loc[threadIdx.x] = 0;
    __syncthreads();
    const int wid = threadIdx.x >> 5, lane = threadIdx.x & 31;
    const int t = blockIdx.x * 8 + wid;
    const float* xr = x + (size_t)t * C;
    float acc[8] = {0.f, 0.f, 0.f, 0.f, 0.f, 0.f, 0.f, 0.f};
    for (int c = lane; c < C; c += 32) {
        const float xv = xr[c];
        const float4* w4 = reinterpret_cast<const float4*>(wr + (size_t)c * E);
        const float4 a = w4[0], b = w4[1];
        acc[0] += xv * a.x; acc[1] += xv * a.y; acc[2] += xv * a.z; acc[3] += xv * a.w;
        acc[4] += xv * b.x; acc[5] += xv * b.y; acc[6] += xv * b.z; acc[7] += xv * b.w;
    }
    #pragma unroll
    for (int j = 0; j < 8; j++)
        #pragma unroll
        for (int o = 16; o; o >>= 1)
            acc[j] += __shfl_xor_sync(0xFFFFFFFFu, acc[j], o);
    if (lane == 0) {
        float best = -1e30f; int bi = 0;
        #pragma unroll
        for (int j = 0; j < 8; j++) {
            const float v = acc[j] + br[j];
            if (v > best) { best = v; bi = j; }   // first-max, matches argmax
        }
        g_top1[t] = bi;
        atomicAdd(&loc[bi], 1);
    }
    __syncthreads();
    if (threadIdx.x < E) atomicAdd(&g_counts[threadIdx.x], loc[threadIdx.x]);
    __threadfence();
    __syncthreads();
    if (threadIdx.x == 0) {
        if (atomicAdd(&g_done, 1) == (int)gridDim.x - 1) {
            int s = 0, tt = 0;
            for (int e = 0; e < E; e++) {
                g_offsets[e] = s;
                g_cursors[e] = s;
                const int cnt = g_counts[e];
                for (int mt = 0; mt * BM < cnt; mt++)
                    g_tiles[tt++] = (e << 16) | mt;
                s += cnt;
            }
            g_ntiles = tt;
            __threadfence();
        }
    }
}

// Fused map + gather: block per token; claim slot, copy fp32 row -> fp16.
__global__ void k_mapgather(const float* __restrict__ x) {
    const int t = blockIdx.x;
    __shared__ int rs;
    if (threadIdx.x == 0) {
        const int e = g_top1[t];
        const int pos = atomicAdd(&g_cursors[e], 1);
        g_tokof[pos] = t;
        rs = pos;
    }
    __syncthreads();
    const int r = rs;
    const float4 v = reinterpret_cast<const float4*>(x + (size_t)t * C)[threadIdx.x];
    __half2* dst = reinterpret_cast<__half2*>(g_Xg + (size_t)r * C) + threadIdx.x * 2;
    dst[0] = __floats2half2_rn(v.x, v.y);
    dst[1] = __floats2half2_rn(v.z, v.w);
}

// ============================================================================
// Stage 2: grouped GEMM via mma.sync (HMMA, fp16 in / fp32 accum)
//   PHASE1: Hg = gelu(Xg @ w1[e] + b1[e])    (M=cnt, N=4096, K=1024)
//   PHASE2: out[tok] = Hg @ w2[e] + b2[e]    (M=cnt, N=1024, K=4096)
// A: [M][K] rows (ldmatrix), B: [K][N] K-major rows (ldmatrix.trans).
// BM=128, BN=64, BK=128. 8 warps (4x2 grid, 32x32 warp tile), 2-stage
// cp.async (one barrier per 128-wide K-chunk), 2 CTAs/SM.
// ============================================================================
static constexpr int A_TILE_B = BM * BK * 2;              // 32 KB (256B rows)
static constexpr int B_TILE_B = BK * BN * 2;              // 16 KB (128B rows)
static constexpr int STAGE_B  = A_TILE_B + B_TILE_B;      // 48 KB
static constexpr int GEMM_SMEM = 2 * STAGE_B;             // 96 KB

template<bool PHASE1>
__global__ void __launch_bounds__(256, 2)
moe_gemm(const float* __restrict__ bias, float* __restrict__ out) {
    constexpr int KT = PHASE1 ? C : H;
    constexpr int NT = PHASE1 ? H : C;
    constexpr int NK = KT / BK;           // 8 / 32

    extern __shared__ __align__(1024) char smem[];

    if ((int)blockIdx.y >= g_ntiles) return;
    const int pk  = g_tiles[blockIdx.y];
    const int e   = pk >> 16;
    const int m0  = (pk & 0xFFFF) * BM;
    const int cnt = g_counts[e];

    const int tid  = threadIdx.x;
    const int wid  = tid >> 5, lane = tid & 31;
    const int wm   = wid >> 1, wn = wid & 1;      // 4 x 2 warp grid (32x32)
    const int base = g_offsets[e];
    const int valid = min(BM, cnt - m0);
    const int n0   = blockIdx.x * BN;

    const __half* Ag = (PHASE1 ? g_Xg : g_Hg) + (size_t)(base + m0) * KT;
    const __half* Bg = (PHASE1 ? g_w1c : g_w2c) + (size_t)e * KT * NT + n0;
    const uint32_t sb = smem_u32(smem);

    // A loader: 128 rows x 16 chunks (256B rows): thread -> row tid>>1,
    // chunks (tid&1)*8 .. +7
    const int arow = tid >> 1, acb = (tid & 1) * 8;
    // B loader: 128 rows x 8 chunks (128B rows): thread -> row tid>>1,
    // chunks (tid&1)*4 .. +3
    const int brow = tid >> 1, bcb = (tid & 1) * 4;

    auto issue = [&](int kc, int st) {
        const uint32_t As = sb + (uint32_t)st * STAGE_B;
        const uint32_t Bs = As + A_TILE_B;
        const int rA = (arow < valid) ? arow : 0;
        const __half* asrc = Ag + (size_t)rA * KT + kc * BK + acb * 8;
        const int avalid = (arow < valid) ? 16 : 0;
        #pragma unroll
        for (int cc = 0; cc < 8; cc++)
            cp16(As + swz256(arow, acb + cc), asrc + cc * 8, avalid);
        const __half* bsrc = Bg + (size_t)(kc * BK + brow) * NT + bcb * 8;
        #pragma unroll
        for (int cc = 0; cc < 4; cc++)
            cp16(Bs + swz128(brow, bcb + cc), bsrc + cc * 8, 16);
        CP_COMMIT();
    };

    const int l15 = lane & 15, hi = lane >> 4;

    float acc[2][4][4];
    #pragma unroll
    for (int i = 0; i < 2; i++)
        #pragma unroll
        for (int j = 0; j < 4; j++)
            #pragma unroll
            for (int k = 0; k < 4; k++) acc[i][j][k] = 0.f;

    issue(0, 0);
    for (int kc = 0; kc < NK; kc++) {
        CP_WAIT(0);
        __syncthreads();
        if (kc + 1 < NK) issue(kc + 1, (kc + 1) & 1);

        const uint32_t As = sb + (uint32_t)(kc & 1) * STAGE_B;
        const uint32_t Bs = As + A_TILE_B;

        #pragma unroll
        for (int s = 0; s < 8; s++) {             // 8 x k16 phases per chunk
            uint32_t a[2][4], b[2][4];
            const int ch = s * 2 + hi;            // 0..15 within 256B A rows
            #pragma unroll
            for (int i = 0; i < 2; i++) {
                const int row = wm * 32 + i * 16 + l15;
                ldsm4(a[i], As + swz256(row, ch));
            }
            const int krow = s * 16 + l15;        // 0..127 B K-rows
            #pragma unroll
            for (int jj = 0; jj < 2; jj++) {
                const int ncol = wn * 32 + jj * 16 + hi * 8;
                ldsm4t(b[jj], Bs + swz128(krow, ncol >> 3));
            }
            #pragma unroll
            for (int i = 0; i < 2; i++)
                #pragma unroll
                for (int j = 0; j < 4; j++) {
                    const int jj = j >> 1, f = j & 1;
                    mma16816(acc[i][j], a[i], b[jj][f * 2], b[jj][f * 2 + 1]);
                }
        }
    }

    // Epilogue: thread holds rows {g, g+8} of each 16-row frag, cols 2q,2q+1
    const int g = lane >> 2, q = lane & 3;
    const float* bp = bias + (size_t)e * NT;
    #pragma unroll
    for (int i = 0; i < 2; i++) {
        #pragma unroll
        for (int hr = 0; hr < 2; hr++) {
            const int row = wm * 32 + i * 16 + g + hr * 8;
            if (row >= valid) continue;
            #pragma unroll
            for (int j = 0; j < 4; j++) {
                const int col = n0 + wn * 32 + j * 8 + q * 2;
                float v0 = acc[i][j][hr * 2 + 0] + bp[col];
                float v1 = acc[i][j][hr * 2 + 1] + bp[col + 1];
                if (PHASE1) {
                    v0 = 0.5f * v0 * (1.0f + erff(v0 * 0.70710678118654752f));
                    v1 = 0.5f * v1 * (1.0f + erff(v1 * 0.70710678118654752f));
                    *reinterpret_cast<__half2*>(
                        g_Hg + (size_t)(base + m0 + row) * H + col) =
                        __floats2half2_rn(v0, v1);
                } else {
                    const int tok = g_tokof[base + m0 + row];
                    float2 v; v.x = v0; v.y = v1;
                    *reinterpret_cast<float2*>(
                        out + (size_t)tok * C + col) = v;
                }
            }
        }
    }
}

// ============================================================================
// kernel_launch  (GEMM1 is OUR launch #4)
// ============================================================================
extern "C" void kernel_launch(void* const* d_in, const int* in_sizes, int n_in,
                              void* d_out, int out_size) {
    const float* x  = (const float*)d_in[0];
    const float* wr = (const float*)d_in[1];
    const float* br = (const float*)d_in[2];
    const float* w1 = (const float*)d_in[3];
    const float* b1 = (const float*)d_in[4];
    const float* w2 = (const float*)d_in[5];
    const float* b2 = (const float*)d_in[6];
    float* out = (float*)d_out;

    cudaFuncSetAttribute(moe_gemm<true>,
                         cudaFuncAttributeMaxDynamicSharedMemorySize, GEMM_SMEM);
    cudaFuncSetAttribute(moe_gemm<false>,
                         cudaFuncAttributeMaxDynamicSharedMemorySize, GEMM_SMEM);

    constexpr int N4 = (E * C * H) / 4;          // 8.39M float4s per weight tensor
    __half* w1c; cudaGetSymbolAddress((void**)&w1c, g_w1c);
    __half* w2c; cudaGetSymbolAddress((void**)&w2c, g_w2c);

    k_convert<<<4096, 256>>>(w1, w2, w1c, w2c, N4);   // #1 (+zero counters)
    k_router<<<NTOK / 8, 256>>>(x, wr, br);            // #2 (+count +scan +tiles)
    k_mapgather<<<NTOK, 256>>>(x);                     // #3
    moe_gemm<true><<<dim3(H / BN, MAX_TILES), 256, GEMM_SMEM>>>(b1, nullptr);  // #4
    moe_gemm<false><<<dim3(C / BN, MAX_TILES), 256, GEMM_SMEM>>>(b2, out);     // #5
}

// round 16
// speedup vs baseline: 1.9781x; 1.9781x over previous
#include <cuda_runtime.h>
#include <cuda_fp16.h>
#include <cstdint>

// ============================================================================
// Problem dims (fixed): x [4,2048,1024], E=8 experts, H=4096
// ============================================================================
static constexpr int NTOK = 8192;   // B*T
static constexpr int C    = 1024;
static constexpr int H    = 4096;
static constexpr int E    = 8;

static constexpr int BM = 128, BN = 64, BK = 64;
static constexpr int MAX_TILES = 72;    // sum ceil(cnt_e/BM) <= 64 + 7

// ============================================================================
// Scratch (static __device__ — no allocation allowed)
// ============================================================================
__device__ __half g_w1c[(size_t)E * C * H];   // fp16 copy of w1, [E][C][H] (K-major)
__device__ __half g_w2c[(size_t)E * H * C];   // fp16 copy of w2, [E][H][C] (K-major)
__device__ __half g_Xg [(size_t)NTOK * C];    // gathered tokens, fp16
__device__ __half g_Hg [(size_t)NTOK * H];    // hidden activations, fp16
__device__ int    g_top1[NTOK];
__device__ int    g_tokof[NTOK];
__device__ int    g_counts[E];
__device__ int    g_offsets[E];
__device__ int    g_cursors[E];
__device__ int    g_done;
__device__ int    g_ntiles;
__device__ int    g_tiles[MAX_TILES];          // (e << 16) | m_tile

#define DI __device__ __forceinline__

DI uint32_t smem_u32(const void* p) {
    uint32_t r;
    asm("{ .reg .u64 t; cvta.to.shared.u64 t, %1; cvt.u32.u64 %0, t; }"
        : "=r"(r) : "l"(p));
    return r;
}

// 16B async copy, zero-fill when srcsize==0
DI void cp16(uint32_t dst, const void* src, int srcsize) {
    asm volatile("cp.async.cg.shared.global [%0], [%1], 16, %2;"
                 :: "r"(dst), "l"(src), "r"(srcsize) : "memory");
}
#define CP_COMMIT() asm volatile("cp.async.commit_group;" ::: "memory")
#define CP_WAIT(n)  asm volatile("cp.async.wait_group %0;" :: "n"(n) : "memory")

DI void ldsm4(uint32_t* r, uint32_t addr) {
    asm volatile("ldmatrix.sync.aligned.m8n8.x4.shared.b16 {%0,%1,%2,%3}, [%4];"
                 : "=r"(r[0]), "=r"(r[1]), "=r"(r[2]), "=r"(r[3]) : "r"(addr));
}

DI void ldsm4t(uint32_t* r, uint32_t addr) {
    asm volatile("ldmatrix.sync.aligned.m8n8.x4.trans.shared.b16 {%0,%1,%2,%3}, [%4];"
                 : "=r"(r[0]), "=r"(r[1]), "=r"(r[2]), "=r"(r[3]) : "r"(addr));
}

DI void mma16816(float* d, const uint32_t* a, uint32_t b0, uint32_t b1) {
    asm volatile(
        "mma.sync.aligned.m16n8k16.row.col.f32.f16.f16.f32 "
        "{%0,%1,%2,%3}, {%4,%5,%6,%7}, {%8,%9}, {%0,%1,%2,%3};"
        : "+f"(d[0]), "+f"(d[1]), "+f"(d[2]), "+f"(d[3])
        : "r"(a[0]), "r"(a[1]), "r"(a[2]), "r"(a[3]), "r"(b0), "r"(b1));
}

// 128B tile rows (64 halves), 8x16B chunks, chunk ^= row&7 -> conflict-free
// for cp.async stores and both ldmatrix variants. Used for A and B tiles.
DI uint32_t swz(int row, int chunk) {
    return (uint32_t)(row * 128 + ((chunk ^ (row & 7)) << 4));
}

// fp32 float4 -> fp16 uint2 convert helper
DI uint2 cvt4(const float4 v) {
    __half2 h0 = __floats2half2_rn(v.x, v.y);
    __half2 h1 = __floats2half2_rn(v.z, v.w);
    uint2 pk;
    pk.x = *reinterpret_cast<uint32_t*>(&h0);
    pk.y = *reinterpret_cast<uint32_t*>(&h1);
    return pk;
}

// ============================================================================
// Stage 1: setup kernels
// ============================================================================

// Streaming fp32 -> fp16 convert of w1 ONLY (w2 converts inside GEMM1).
__global__ void k_convert(const float* __restrict__ w1, __half* __restrict__ w1c,
                          int n4) {
    if (blockIdx.x == 0 && threadIdx.x <= E) {
        if (threadIdx.x < E) g_counts[threadIdx.x] = 0;
        else                 g_done = 0;
    }
    const int stride = gridDim.x * blockDim.x;
    for (int i = blockIdx.x * blockDim.x + threadIdx.x; i < n4; i += stride)
        reinterpret_cast<uint2*>(w1c)[i] =
            cvt4(reinterpret_cast<const float4*>(w1)[i]);
}

// Router + histogram + (last block) scan + tile table.
__global__ void k_router(const float* __restrict__ x,
                         const float* __restrict__ wr,
                         const float* __restrict__ br) {
    __shared__ int loc[E];
    if (threadIdx.x < E) loc[threadIdx.x] = 0;
    __syncthreads();
    const int wid = threadIdx.x >> 5, lane = threadIdx.x & 31;
    const int t = blockIdx.x * 8 + wid;
    const float* xr = x + (size_t)t * C;
    float acc[8] = {0.f, 0.f, 0.f, 0.f, 0.f, 0.f, 0.f, 0.f};
    for (int c = lane; c < C; c += 32) {
        const float xv = xr[c];
        const float4* w4 = reinterpret_cast<const float4*>(wr + (size_t)c * E);
        const float4 a = w4[0], b = w4[1];
        acc[0] += xv * a.x; acc[1] += xv * a.y; acc[2] += xv * a.z; acc[3] += xv * a.w;
        acc[4] += xv * b.x; acc[5] += xv * b.y; acc[6] += xv * b.z; acc[7] += xv * b.w;
    }
    #pragma unroll
    for (int j = 0; j < 8; j++)
        #pragma unroll
        for (int o = 16; o; o >>= 1)
            acc[j] += __shfl_xor_sync(0xFFFFFFFFu, acc[j], o);
    if (lane == 0) {
        float best = -1e30f; int bi = 0;
        #pragma unroll
        for (int j = 0; j < 8; j++) {
            const float v = acc[j] + br[j];
            if (v > best) { best = v; bi = j; }   // first-max, matches argmax
        }
        g_top1[t] = bi;
        atomicAdd(&loc[bi], 1);
    }
    __syncthreads();
    if (threadIdx.x < E) atomicAdd(&g_counts[threadIdx.x], loc[threadIdx.x]);
    __threadfence();
    __syncthreads();
    if (threadIdx.x == 0) {
        if (atomicAdd(&g_done, 1) == (int)gridDim.x - 1) {
            int s = 0, tt = 0;
            for (int e = 0; e < E; e++) {
                g_offsets[e] = s;
                g_cursors[e] = s;
                const int cnt = g_counts[e];
                for (int mt = 0; mt * BM < cnt; mt++)
                    g_tiles[tt++] = (e << 16) | mt;
                s += cnt;
            }
            g_ntiles = tt;
            __threadfence();
        }
    }
}

// Fused map + gather: block per token; claim slot, copy fp32 row -> fp16.
__global__ void k_mapgather(const float* __restrict__ x) {
    const int t = blockIdx.x;
    __shared__ int rs;
    if (threadIdx.x == 0) {
        const int e = g_top1[t];
        const int pos = atomicAdd(&g_cursors[e], 1);
        g_tokof[pos] = t;
        rs = pos;
    }
    __syncthreads();
    const int r = rs;
    const float4 v = reinterpret_cast<const float4*>(x + (size_t)t * C)[threadIdx.x];
    __half2* dst = reinterpret_cast<__half2*>(g_Xg + (size_t)r * C) + threadIdx.x * 2;
    dst[0] = __floats2half2_rn(v.x, v.y);
    dst[1] = __floats2half2_rn(v.z, v.w);
}

// ============================================================================
// Stage 2: grouped GEMM via mma.sync (HMMA, fp16 in / fp32 accum)
//   PHASE1: Hg = gelu(Xg @ w1[e] + b1[e])    (M=cnt, N=4096, K=1024)
//           + blockIdx.y==0 row converts w2 fp32->fp16 (overlapped)
//   PHASE2: out[tok] = Hg @ w2[e] + b2[e]    (M=cnt, N=1024, K=4096)
// A: [M][K] rows (ldmatrix), B: [K][N] K-major rows (ldmatrix.trans).
// BM=128, BN=64, BK=64. 8 warps (4x2 grid, 32x32 warp tile), 3-stage
// cp.async, one __syncthreads per K-chunk, 3 CTAs/SM (24 warps).
// ============================================================================
static constexpr int A_TILE_B = BM * BK * 2;              // 16 KB
static constexpr int B_TILE_B = BK * BN * 2;              //  8 KB
static constexpr int STAGE_B  = A_TILE_B + B_TILE_B;      // 24 KB
static constexpr int NSTAGE   = 3;
static constexpr int GEMM_SMEM = NSTAGE * STAGE_B;        // 72 KB

template<bool PHASE1>
__global__ void __launch_bounds__(256, 3)
moe_gemm(const float* __restrict__ bias, float* __restrict__ out,
         const float* __restrict__ csrc, __half* __restrict__ cdst, int cn4) {
    constexpr int KT = PHASE1 ? C : H;
    constexpr int NT = PHASE1 ? H : C;
    constexpr int NK = KT / BK;

    extern __shared__ __align__(1024) char smem[];

    // Row 0: overlapped streaming convert (w2 during PHASE1), scheduled first.
    if (blockIdx.y == 0) {
        if (cn4) {
            const int stride = gridDim.x * blockDim.x;
            for (int i = blockIdx.x * blockDim.x + threadIdx.x; i < cn4; i += stride)
                reinterpret_cast<uint2*>(cdst)[i] =
                    cvt4(reinterpret_cast<const float4*>(csrc)[i]);
        }
        return;
    }

    const int ty = (int)blockIdx.y - 1;
    if (ty >= g_ntiles) return;
    const int pk  = g_tiles[ty];
    const int e   = pk >> 16;
    const int m0  = (pk & 0xFFFF) * BM;
    const int cnt = g_counts[e];

    const int tid  = threadIdx.x;
    const int wid  = tid >> 5, lane = tid & 31;
    const int wm   = wid >> 1, wn = wid & 1;      // 4 x 2 warp grid (32x32)
    const int base = g_offsets[e];
    const int valid = min(BM, cnt - m0);
    const int n0   = blockIdx.x * BN;

    const __half* Ag = (PHASE1 ? g_Xg : g_Hg) + (size_t)(base + m0) * KT;
    const __half* Bg = (PHASE1 ? g_w1c : g_w2c) + (size_t)e * KT * NT + n0;
    const uint32_t sb = smem_u32(smem);

    // loader mapping: rows (tid>>3)+32h, 16B chunk gc (8 per 128B row)
    const int gr = tid >> 3, gc = tid & 7;

    auto issue = [&](int kc, int st) {
        const uint32_t As = sb + (uint32_t)st * STAGE_B;
        const uint32_t Bs = As + A_TILE_B;
        #pragma unroll
        for (int h = 0; h < 4; h++) {             // A: 128 rows x 128B
            const int row = gr + h * 32;
            const int rA = (row < valid) ? row : 0;
            cp16(As + swz(row, gc), Ag + (size_t)rA * KT + kc * BK + gc * 8,
                 (row < valid) ? 16 : 0);
        }
        #pragma unroll
        for (int h = 0; h < 2; h++) {             // B: 64 K-rows x 128B (BN=64)
            const int krow = gr + h * 32;
            cp16(Bs + swz(krow, gc),
                 Bg + (size_t)(kc * BK + krow) * NT + gc * 8, 16);
        }
        CP_COMMIT();
    };

    const int l15 = lane & 15, hi = lane >> 4;

    float acc[2][4][4];
    #pragma unroll
    for (int i = 0; i < 2; i++)
        #pragma unroll
        for (int j = 0; j < 4; j++)
            #pragma unroll
            for (int k = 0; k < 4; k++) acc[i][j][k] = 0.f;

    issue(0, 0);
    issue(1, 1);
    int ist = 2, cst = 0;
    for (int kc = 0; kc < NK; kc++) {
        if (kc + 1 < NK) { CP_WAIT(1); } else { CP_WAIT(0); }
        __syncthreads();
        if (kc + 2 < NK) {
            issue(kc + 2, ist);
            ist = (ist + 1 == NSTAGE) ? 0 : ist + 1;
        }

        const uint32_t As = sb + (uint32_t)cst * STAGE_B;
        const uint32_t Bs = As + A_TILE_B;
        cst = (cst + 1 == NSTAGE) ? 0 : cst + 1;

        #pragma unroll
        for (int s = 0; s < 4; s++) {             // 4 x k16 phases per chunk
            uint32_t a[2][4], b[2][4];
            const int ch = s * 2 + hi;
            #pragma unroll
            for (int i = 0; i < 2; i++) {
                const int row = wm * 32 + i * 16 + l15;
                ldsm4(a[i], As + swz(row, ch));
            }
            const int krow = s * 16 + l15;
            #pragma unroll
            for (int jj = 0; jj < 2; jj++) {
                const int ncol = wn * 32 + jj * 16 + hi * 8;
                ldsm4t(b[jj], Bs + swz(krow, ncol >> 3));
            }
            #pragma unroll
            for (int i = 0; i < 2; i++)
                #pragma unroll
                for (int j = 0; j < 4; j++) {
                    const int jj = j >> 1, f = j & 1;
                    mma16816(acc[i][j], a[i], b[jj][f * 2], b[jj][f * 2 + 1]);
                }
        }
    }

    // Epilogue: thread holds rows {g, g+8} of each 16-row frag, cols 2q,2q+1
    const int g = lane >> 2, q = lane & 3;
    const float* bp = bias + (size_t)e * NT;
    #pragma unroll
    for (int i = 0; i < 2; i++) {
        #pragma unroll
        for (int hr = 0; hr < 2; hr++) {
            const int row = wm * 32 + i * 16 + g + hr * 8;
            if (row >= valid) continue;
            #pragma unroll
            for (int j = 0; j < 4; j++) {
                const int col = n0 + wn * 32 + j * 8 + q * 2;
                float v0 = acc[i][j][hr * 2 + 0] + bp[col];
                float v1 = acc[i][j][hr * 2 + 1] + bp[col + 1];
                if (PHASE1) {
                    v0 = 0.5f * v0 * (1.0f + erff(v0 * 0.70710678118654752f));
                    v1 = 0.5f * v1 * (1.0f + erff(v1 * 0.70710678118654752f));
                    *reinterpret_cast<__half2*>(
                        g_Hg + (size_t)(base + m0 + row) * H + col) =
                        __floats2half2_rn(v0, v1);
                } else {
                    const int tok = g_tokof[base + m0 + row];
                    float2 v; v.x = v0; v.y = v1;
                    *reinterpret_cast<float2*>(
                        out + (size_t)tok * C + col) = v;
                }
            }
        }
    }
}

// ============================================================================
// kernel_launch  (GEMM1 is OUR launch #4)
// ============================================================================
extern "C" void kernel_launch(void* const* d_in, const int* in_sizes, int n_in,
                              void* d_out, int out_size) {
    const float* x  = (const float*)d_in[0];
    const float* wr = (const float*)d_in[1];
    const float* br = (const float*)d_in[2];
    const float* w1 = (const float*)d_in[3];
    const float* b1 = (const float*)d_in[4];
    const float* w2 = (const float*)d_in[5];
    const float* b2 = (const float*)d_in[6];
    float* out = (float*)d_out;

    cudaFuncSetAttribute(moe_gemm<true>,
                         cudaFuncAttributeMaxDynamicSharedMemorySize, GEMM_SMEM);
    cudaFuncSetAttribute(moe_gemm<false>,
                         cudaFuncAttributeMaxDynamicSharedMemorySize, GEMM_SMEM);

    constexpr int N4 = (E * C * H) / 4;          // 8.39M float4s per weight tensor
    __half* w1c; cudaGetSymbolAddress((void**)&w1c, g_w1c);
    __half* w2c; cudaGetSymbolAddress((void**)&w2c, g_w2c);

    k_convert<<<4096, 256>>>(w1, w1c, N4);             // #1 (w1 + zero counters)
    k_router<<<NTOK / 8, 256>>>(x, wr, br);            // #2 (+count +scan +tiles)
    k_mapgather<<<NTOK, 256>>>(x);                     // #3
    moe_gemm<true><<<dim3(H / BN, MAX_TILES + 1), 256, GEMM_SMEM>>>(
        b1, nullptr, w2, w2c, N4);                     // #4 (+w2 convert overlap)
    moe_gemm<false><<<dim3(C / BN, MAX_TILES + 1), 256, GEMM_SMEM>>>(
        b2, out, nullptr, nullptr, 0);                 // #5
}

// round 17
// speedup vs baseline: 2.0219x; 1.0222x over previous
#include <cuda_runtime.h>
#include <cuda_fp16.h>
#include <cstdint>

// ============================================================================
// Problem dims (fixed): x [4,2048,1024], E=8 experts, H=4096
// ============================================================================
static constexpr int NTOK = 8192;   // B*T
static constexpr int C    = 1024;
static constexpr int H    = 4096;
static constexpr int E    = 8;

static constexpr int BM = 128, BN = 64, BK = 64;
static constexpr int MAX_TILES = 72;    // sum ceil(cnt_e/BM) <= 64 + 7
static constexpr int ROUTER_BLOCKS = NTOK / 8;   // 1024
static constexpr int CONV_BLOCKS   = 3072;       // w1-convert blocks in router launch

// ============================================================================
// Scratch (static __device__ — no allocation allowed; zero at module load)
// ============================================================================
__device__ __half g_w1c[(size_t)E * C * H];   // fp16 copy of w1, [E][C][H] (K-major)
__device__ __half g_w2c[(size_t)E * H * C];   // fp16 copy of w2, [E][H][C] (K-major)
__device__ __half g_Xg [(size_t)NTOK * C];    // gathered tokens, fp16
__device__ __half g_Hg [(size_t)NTOK * H];    // hidden activations, fp16
__device__ int    g_top1[NTOK];
__device__ int    g_tokof[NTOK];
__device__ int    g_counts[E];                // transient; re-zeroed each call
__device__ int    g_offsets[E + 1];
__device__ int    g_cursors[E];
__device__ int    g_done;                     // transient; re-zeroed each call
__device__ int    g_ntiles;
__device__ int    g_tiles[MAX_TILES];         // (e << 16) | m_tile

#define DI __device__ __forceinline__

DI uint32_t smem_u32(const void* p) {
    uint32_t r;
    asm("{ .reg .u64 t; cvta.to.shared.u64 t, %1; cvt.u32.u64 %0, t; }"
        : "=r"(r) : "l"(p));
    return r;
}

// 16B async copy, zero-fill when srcsize==0
DI void cp16(uint32_t dst, const void* src, int srcsize) {
    asm volatile("cp.async.cg.shared.global [%0], [%1], 16, %2;"
                 :: "r"(dst), "l"(src), "r"(srcsize) : "memory");
}
#define CP_COMMIT() asm volatile("cp.async.commit_group;" ::: "memory")
#define CP_WAIT(n)  asm volatile("cp.async.wait_group %0;" :: "n"(n) : "memory")

DI void ldsm4(uint32_t* r, uint32_t addr) {
    asm volatile("ldmatrix.sync.aligned.m8n8.x4.shared.b16 {%0,%1,%2,%3}, [%4];"
                 : "=r"(r[0]), "=r"(r[1]), "=r"(r[2]), "=r"(r[3]) : "r"(addr));
}

DI void ldsm4t(uint32_t* r, uint32_t addr) {
    asm volatile("ldmatrix.sync.aligned.m8n8.x4.trans.shared.b16 {%0,%1,%2,%3}, [%4];"
                 : "=r"(r[0]), "=r"(r[1]), "=r"(r[2]), "=r"(r[3]) : "r"(addr));
}

DI void mma16816(float* d, const uint32_t* a, uint32_t b0, uint32_t b1) {
    asm volatile(
        "mma.sync.aligned.m16n8k16.row.col.f32.f16.f16.f32 "
        "{%0,%1,%2,%3}, {%4,%5,%6,%7}, {%8,%9}, {%0,%1,%2,%3};"
        : "+f"(d[0]), "+f"(d[1]), "+f"(d[2]), "+f"(d[3])
        : "r"(a[0]), "r"(a[1]), "r"(a[2]), "r"(a[3]), "r"(b0), "r"(b1));
}

// 128B tile rows (64 halves), 8x16B chunks, chunk ^= row&7 -> conflict-free
// for cp.async stores and both ldmatrix variants. Used for A and B tiles.
DI uint32_t swz(int row, int chunk) {
    return (uint32_t)(row * 128 + ((chunk ^ (row & 7)) << 4));
}

// fp32 float4 -> fp16 uint2 convert helper
DI uint2 cvt4(const float4 v) {
    __half2 h0 = __floats2half2_rn(v.x, v.y);
    __half2 h1 = __floats2half2_rn(v.z, v.w);
    uint2 pk;
    pk.x = *reinterpret_cast<uint32_t*>(&h0);
    pk.y = *reinterpret_cast<uint32_t*>(&h1);
    return pk;
}

// ============================================================================
// Stage 1: router (+histogram +scan +tiles) fused with w1 fp32->fp16 convert.
// Blocks [0, ROUTER_BLOCKS): router. Blocks [ROUTER_BLOCKS, ...): convert.
// Router's last block builds offsets/tiles then re-zeroes transient state
// so the next graph replay starts clean.
// ============================================================================
__global__ void k_router(const float* __restrict__ x,
                         const float* __restrict__ wr,
                         const float* __restrict__ br,
                         const float* __restrict__ w1,
                         __half* __restrict__ w1c, int n4) {
    if ((int)blockIdx.x >= ROUTER_BLOCKS) {           // convert band
        const int cb = (int)blockIdx.x - ROUTER_BLOCKS;
        const int stride = CONV_BLOCKS * blockDim.x;
        for (int i = cb * blockDim.x + threadIdx.x; i < n4; i += stride)
            reinterpret_cast<uint2*>(w1c)[i] =
                cvt4(reinterpret_cast<const float4*>(w1)[i]);
        return;
    }

    __shared__ int loc[E];
    if (threadIdx.x < E) loc[threadIdx.x] = 0;
    __syncthreads();
    const int wid = threadIdx.x >> 5, lane = threadIdx.x & 31;
    const int t = blockIdx.x * 8 + wid;
    const float* xr = x + (size_t)t * C;
    float acc[8] = {0.f, 0.f, 0.f, 0.f, 0.f, 0.f, 0.f, 0.f};
    for (int c = lane; c < C; c += 32) {
        const float xv = xr[c];
        const float4* w4 = reinterpret_cast<const float4*>(wr + (size_t)c * E);
        const float4 a = w4[0], b = w4[1];
        acc[0] += xv * a.x; acc[1] += xv * a.y; acc[2] += xv * a.z; acc[3] += xv * a.w;
        acc[4] += xv * b.x; acc[5] += xv * b.y; acc[6] += xv * b.z; acc[7] += xv * b.w;
    }
    #pragma unroll
    for (int j = 0; j < 8; j++)
        #pragma unroll
        for (int o = 16; o; o >>= 1)
            acc[j] += __shfl_xor_sync(0xFFFFFFFFu, acc[j], o);
    if (lane == 0) {
        float best = -1e30f; int bi = 0;
        #pragma unroll
        for (int j = 0; j < 8; j++) {
            const float v = acc[j] + br[j];
            if (v > best) { best = v; bi = j; }   // first-max, matches argmax
        }
        g_top1[t] = bi;
        atomicAdd(&loc[bi], 1);
    }
    __syncthreads();
    if (threadIdx.x < E) atomicAdd(&g_counts[threadIdx.x], loc[threadIdx.x]);
    __threadfence();
    __syncthreads();
    if (threadIdx.x == 0) {
        if (atomicAdd(&g_done, 1) == ROUTER_BLOCKS - 1) {
            int s = 0, tt = 0;
            #pragma unroll
            for (int e = 0; e < E; e++) {
                g_offsets[e] = s;
                g_cursors[e] = s;
                const int cnt = g_counts[e];
                for (int mt = 0; mt * BM < cnt; mt++)
                    g_tiles[tt++] = (e << 16) | mt;
                s += cnt;
                g_counts[e] = 0;                  // reset for next replay
            }
            g_offsets[E] = s;
            g_ntiles = tt;
            g_done = 0;                           // reset for next replay
            __threadfence();
        }
    }
}

// Fused map + gather: block per token; claim slot, copy fp32 row -> fp16.
__global__ void k_mapgather(const float* __restrict__ x) {
    const int t = blockIdx.x;
    __shared__ int rs;
    if (threadIdx.x == 0) {
        const int e = g_top1[t];
        const int pos = atomicAdd(&g_cursors[e], 1);
        g_tokof[pos] = t;
        rs = pos;
    }
    __syncthreads();
    const int r = rs;
    const float4 v = reinterpret_cast<const float4*>(x + (size_t)t * C)[threadIdx.x];
    __half2* dst = reinterpret_cast<__half2*>(g_Xg + (size_t)r * C) + threadIdx.x * 2;
    dst[0] = __floats2half2_rn(v.x, v.y);
    dst[1] = __floats2half2_rn(v.z, v.w);
}

// ============================================================================
// Stage 2: grouped GEMM via mma.sync (HMMA, fp16 in / fp32 accum)
//   PHASE1: Hg = gelu(Xg @ w1[e] + b1[e])    (M=cnt, N=4096, K=1024)
//           + blockIdx.y==0 row converts w2 fp32->fp16 (overlapped)
//   PHASE2: out[tok] = Hg @ w2[e] + b2[e]    (M=cnt, N=1024, K=4096)
// A: [M][K] rows (ldmatrix), B: [K][N] K-major rows (ldmatrix.trans).
// BM=128, BN=64, BK=64. 8 warps (4x2 grid, 32x32 warp tile), 3-stage
// cp.async, one __syncthreads per K-chunk, 3 CTAs/SM (24 warps).
// ============================================================================
static constexpr int A_TILE_B = BM * BK * 2;              // 16 KB
static constexpr int B_TILE_B = BK * BN * 2;              //  8 KB
static constexpr int STAGE_B  = A_TILE_B + B_TILE_B;      // 24 KB
static constexpr int NSTAGE   = 3;
static constexpr int GEMM_SMEM = NSTAGE * STAGE_B;        // 72 KB

template<bool PHASE1>
__global__ void __launch_bounds__(256, 3)
moe_gemm(const float* __restrict__ bias, float* __restrict__ out,
         const float* __restrict__ csrc, __half* __restrict__ cdst, int cn4) {
    constexpr int KT = PHASE1 ? C : H;
    constexpr int NT = PHASE1 ? H : C;
    constexpr int NK = KT / BK;

    extern __shared__ __align__(1024) char smem[];

    // Row 0: overlapped streaming convert (w2 during PHASE1), scheduled first.
    if (blockIdx.y == 0) {
        if (cn4) {
            const int stride = gridDim.x * blockDim.x;
            for (int i = blockIdx.x * blockDim.x + threadIdx.x; i < cn4; i += stride)
                reinterpret_cast<uint2*>(cdst)[i] =
                    cvt4(reinterpret_cast<const float4*>(csrc)[i]);
        }
        return;
    }

    const int ty = (int)blockIdx.y - 1;
    if (ty >= g_ntiles) return;
    const int pk  = g_tiles[ty];
    const int e   = pk >> 16;
    const int m0  = (pk & 0xFFFF) * BM;
    const int base = g_offsets[e];
    const int cnt  = g_offsets[e + 1] - base;

    const int tid  = threadIdx.x;
    const int wid  = tid >> 5, lane = tid & 31;
    const int wm   = wid >> 1, wn = wid & 1;      // 4 x 2 warp grid (32x32)
    const int valid = min(BM, cnt - m0);
    const int n0   = blockIdx.x * BN;

    const __half* Ag = (PHASE1 ? g_Xg : g_Hg) + (size_t)(base + m0) * KT;
    const __half* Bg = (PHASE1 ? g_w1c : g_w2c) + (size_t)e * KT * NT + n0;
    const uint32_t sb = smem_u32(smem);

    // loader mapping: rows (tid>>3)+32h, 16B chunk gc (8 per 128B row)
    const int gr = tid >> 3, gc = tid & 7;

    auto issue = [&](int kc, int st) {
        const uint32_t As = sb + (uint32_t)st * STAGE_B;
        const uint32_t Bs = As + A_TILE_B;
        #pragma unroll
        for (int h = 0; h < 4; h++) {             // A: 128 rows x 128B
            const int row = gr + h * 32;
            const int rA = (row < valid) ? row : 0;
            cp16(As + swz(row, gc), Ag + (size_t)rA * KT + kc * BK + gc * 8,
                 (row < valid) ? 16 : 0);
        }
        #pragma unroll
        for (int h = 0; h < 2; h++) {             // B: 64 K-rows x 128B (BN=64)
            const int krow = gr + h * 32;
            cp16(Bs + swz(krow, gc),
                 Bg + (size_t)(kc * BK + krow) * NT + gc * 8, 16);
        }
        CP_COMMIT();
    };

    const int l15 = lane & 15, hi = lane >> 4;

    float acc[2][4][4];
    #pragma unroll
    for (int i = 0; i < 2; i++)
        #pragma unroll
        for (int j = 0; j < 4; j++)
            #pragma unroll
            for (int k = 0; k < 4; k++) acc[i][j][k] = 0.f;

    issue(0, 0);
    issue(1, 1);
    int ist = 2, cst = 0;
    for (int kc = 0; kc < NK; kc++) {
        if (kc + 1 < NK) { CP_WAIT(1); } else { CP_WAIT(0); }
        __syncthreads();
        if (kc + 2 < NK) {
            issue(kc + 2, ist);
            ist = (ist + 1 == NSTAGE) ? 0 : ist + 1;
        }

        const uint32_t As = sb + (uint32_t)cst * STAGE_B;
        const uint32_t Bs = As + A_TILE_B;
        cst = (cst + 1 == NSTAGE) ? 0 : cst + 1;

        #pragma unroll
        for (int s = 0; s < 4; s++) {             // 4 x k16 phases per chunk
            uint32_t a[2][4], b[2][4];
            const int ch = s * 2 + hi;
            #pragma unroll
            for (int i = 0; i < 2; i++) {
                const int row = wm * 32 + i * 16 + l15;
                ldsm4(a[i], As + swz(row, ch));
            }
            const int krow = s * 16 + l15;
            #pragma unroll
            for (int jj = 0; jj < 2; jj++) {
                const int ncol = wn * 32 + jj * 16 + hi * 8;
                ldsm4t(b[jj], Bs + swz(krow, ncol >> 3));
            }
            #pragma unroll
            for (int i = 0; i < 2; i++)
                #pragma unroll
                for (int j = 0; j < 4; j++) {
                    const int jj = j >> 1, f = j & 1;
                    mma16816(acc[i][j], a[i], b[jj][f * 2], b[jj][f * 2 + 1]);
                }
        }
    }

    // Epilogue: thread holds rows {g, g+8} of each 16-row frag, cols 2q,2q+1
    const int g = lane >> 2, q = lane & 3;
    const float* bp = bias + (size_t)e * NT;
    #pragma unroll
    for (int i = 0; i < 2; i++) {
        #pragma unroll
        for (int hr = 0; hr < 2; hr++) {
            const int row = wm * 32 + i * 16 + g + hr * 8;
            if (row >= valid) continue;
            #pragma unroll
            for (int j = 0; j < 4; j++) {
                const int col = n0 + wn * 32 + j * 8 + q * 2;
                float v0 = acc[i][j][hr * 2 + 0] + bp[col];
                float v1 = acc[i][j][hr * 2 + 1] + bp[col + 1];
                if (PHASE1) {
                    v0 = 0.5f * v0 * (1.0f + erff(v0 * 0.70710678118654752f));
                    v1 = 0.5f * v1 * (1.0f + erff(v1 * 0.70710678118654752f));
                    *reinterpret_cast<__half2*>(
                        g_Hg + (size_t)(base + m0 + row) * H + col) =
                        __floats2half2_rn(v0, v1);
                } else {
                    const int tok = g_tokof[base + m0 + row];
                    float2 v; v.x = v0; v.y = v1;
                    *reinterpret_cast<float2*>(
                        out + (size_t)tok * C + col) = v;
                }
            }
        }
    }
}

// ============================================================================
// kernel_launch  (4 launches; GEMM2 is OUR launch #4 -> profiled by ncu)
// ============================================================================
extern "C" void kernel_launch(void* const* d_in, const int* in_sizes, int n_in,
                              void* d_out, int out_size) {
    const float* x  = (const float*)d_in[0];
    const float* wr = (const float*)d_in[1];
    const float* br = (const float*)d_in[2];
    const float* w1 = (const float*)d_in[3];
    const float* b1 = (const float*)d_in[4];
    const float* w2 = (const float*)d_in[5];
    const float* b2 = (const float*)d_in[6];
    float* out = (float*)d_out;

    cudaFuncSetAttribute(moe_gemm<true>,
                         cudaFuncAttributeMaxDynamicSharedMemorySize, GEMM_SMEM);
    cudaFuncSetAttribute(moe_gemm<false>,
                         cudaFuncAttributeMaxDynamicSharedMemorySize, GEMM_SMEM);

    constexpr int N4 = (E * C * H) / 4;          // 8.39M float4s per weight tensor
    __half* w1c; cudaGetSymbolAddress((void**)&w1c, g_w1c);
    __half* w2c; cudaGetSymbolAddress((void**)&w2c, g_w2c);

    k_router<<<ROUTER_BLOCKS + CONV_BLOCKS, 256>>>(x, wr, br, w1, w1c, N4);  // #1
    k_mapgather<<<NTOK, 256>>>(x);                                            // #2
    moe_gemm<true><<<dim3(H / BN, MAX_TILES + 1), 256, GEMM_SMEM>>>(
        b1, nullptr, w2, w2c, N4);                                            // #3
    moe_gemm<false><<<dim3(C / BN, MAX_TILES + 1), 256, GEMM_SMEM>>>(
        b2, out, nullptr, nullptr, 0);                                        // #4
}